// round 13
// baseline (speedup 1.0000x reference)
#include <cuda_runtime.h>

// Problem constants
#define BB     32
#define CC     16
#define IN_H   64
#define IN_W   64
#define OUT_H  60
#define OUT_W  60
#define KK     5
#define JT     4               // pixels per (one-warp) block
#define NTHREADS 32
#define CSTRIDE ((size_t)IN_H * IN_W * BB)

typedef unsigned long long ull;

// Scratch: transposed input inT[c][y][x][b]  (batch contiguous 128B lines)
__device__ float g_inT[CC * IN_H * IN_W * BB];

// ---------------------------------------------------------------------------
// Pre-kernel: in[b][c][y][x] -> inT[c][y][x][b]
// ---------------------------------------------------------------------------
__global__ void transpose_kernel(const float* __restrict__ in) {
    __shared__ float s[IN_W][BB + 1];
    const int c = blockIdx.x;
    const int y = blockIdx.y;
    const int t = threadIdx.x;          // 256 threads

    #pragma unroll
    for (int it = 0; it < 8; ++it) {
        int n = t + it * 256;           // 0..2047
        int x = n & 63;
        int b = n >> 6;
        s[x][b] = in[((b * CC + c) * IN_H + y) * IN_W + x];
    }
    __syncthreads();

    float* dst = g_inT + (size_t)(c * IN_H + y) * IN_W * BB;
    #pragma unroll
    for (int it = 0; it < 8; ++it) {
        int n = t + it * 256;
        int b = n & 31;
        int x = n >> 5;
        dst[x * BB + b] = s[x][b];
    }
}

// ---------------------------------------------------------------------------
// f32x2 helpers
// ---------------------------------------------------------------------------
__device__ __forceinline__ ull ffma2(ull a, ull b, ull c) {
    ull d;
    asm("fma.rn.f32x2 %0, %1, %2, %3;" : "=l"(d) : "l"(a), "l"(b), "l"(c));
    return d;
}
__device__ __forceinline__ ull pack2(float x, float y) {
    ull r;
    asm("mov.b64 %0, {%1, %2};" : "=l"(r) : "f"(x), "f"(y));
    return r;
}
__device__ __forceinline__ void unpack2(ull v, float& x, float& y) {
    asm("mov.b64 {%0, %1}, %2;" : "=f"(x), "=f"(y) : "l"(v));
}

// ---------------------------------------------------------------------------
// Main kernel.
//   grid (15, 60): block = ONE WARP covering 4 pixels (row i, cols j0..j0+3).
//   lane = pl (pixel, 2b) x bq2 (batch octet, 2b) x kh (ko octet, 1b).
//   thread = 8 batches x 8 k_out = 32 f32x2 accumulators (64 regs).
// Per (c,u,v): 2 input LDG.128 + 2 weight LDG.128 = 16 L1-cyc,
//              32 FFMA2 = 16 SM-FMA-cyc  -> balanced 1:1.
// 900 one-warp CTAs -> fine-grained SM load balancing, no barriers in loop.
// ---------------------------------------------------------------------------
__global__ __launch_bounds__(NTHREADS, 16)
void lc_kernel(const float* __restrict__ wgt, float* __restrict__ out) {
    __shared__ float so[BB * CC * JT];   // 2048 floats, epilogue staging

    const int j0   = blockIdx.x * JT;
    const int i    = blockIdx.y;
    const int lane = threadIdx.x;
    const int pl   = lane >> 3;                 // pixel 0..3
    const int bq2  = (lane >> 1) & 3;           // batch octet 0..3
    const int kh   = lane & 1;                  // ko octet 0..1
    const int j    = j0 + pl;

    // input: g_inT[c][i+u][j+v][bq2*8 .. +7]
    const float* ip = g_inT + ((size_t)i * IN_W + j) * BB + bq2 * 8;
    // weights: wgt[(i*60+j)*6400 + c*400 + (u*5+v)*16 + kh*8 .. +7]
    const float* wp = wgt + (size_t)(i * OUT_W + j) * (CC * KK * KK * CC) + kh * 8;

    ull acc[4][8];
    #pragma unroll
    for (int p = 0; p < 4; ++p)
        #pragma unroll
        for (int k = 0; k < 8; ++k) acc[p][k] = 0ull;

    for (int c = 0; c < CC; ++c) {
        const float* ipu = ip;
        #pragma unroll 1
        for (int u = 0; u < KK; ++u) {
            #pragma unroll
            for (int v = 0; v < KK; ++v) {
                // loads first: ptxas front-batches these for MLP
                float4 x0 = *(const float4*)(ipu + v * BB);
                float4 x1 = *(const float4*)(ipu + v * BB + 4);
                float4 w0 = *(const float4*)(wp + v * 16);
                float4 w1 = *(const float4*)(wp + v * 16 + 4);

                ull xp0 = pack2(x0.x, x0.y);
                ull xp1 = pack2(x0.z, x0.w);
                ull xp2 = pack2(x1.x, x1.y);
                ull xp3 = pack2(x1.z, x1.w);

                ull ws;
                ws = pack2(w0.x, w0.x);
                acc[0][0] = ffma2(xp0, ws, acc[0][0]);
                acc[1][0] = ffma2(xp1, ws, acc[1][0]);
                acc[2][0] = ffma2(xp2, ws, acc[2][0]);
                acc[3][0] = ffma2(xp3, ws, acc[3][0]);
                ws = pack2(w0.y, w0.y);
                acc[0][1] = ffma2(xp0, ws, acc[0][1]);
                acc[1][1] = ffma2(xp1, ws, acc[1][1]);
                acc[2][1] = ffma2(xp2, ws, acc[2][1]);
                acc[3][1] = ffma2(xp3, ws, acc[3][1]);
                ws = pack2(w0.z, w0.z);
                acc[0][2] = ffma2(xp0, ws, acc[0][2]);
                acc[1][2] = ffma2(xp1, ws, acc[1][2]);
                acc[2][2] = ffma2(xp2, ws, acc[2][2]);
                acc[3][2] = ffma2(xp3, ws, acc[3][2]);
                ws = pack2(w0.w, w0.w);
                acc[0][3] = ffma2(xp0, ws, acc[0][3]);
                acc[1][3] = ffma2(xp1, ws, acc[1][3]);
                acc[2][3] = ffma2(xp2, ws, acc[2][3]);
                acc[3][3] = ffma2(xp3, ws, acc[3][3]);
                ws = pack2(w1.x, w1.x);
                acc[0][4] = ffma2(xp0, ws, acc[0][4]);
                acc[1][4] = ffma2(xp1, ws, acc[1][4]);
                acc[2][4] = ffma2(xp2, ws, acc[2][4]);
                acc[3][4] = ffma2(xp3, ws, acc[3][4]);
                ws = pack2(w1.y, w1.y);
                acc[0][5] = ffma2(xp0, ws, acc[0][5]);
                acc[1][5] = ffma2(xp1, ws, acc[1][5]);
                acc[2][5] = ffma2(xp2, ws, acc[2][5]);
                acc[3][5] = ffma2(xp3, ws, acc[3][5]);
                ws = pack2(w1.z, w1.z);
                acc[0][6] = ffma2(xp0, ws, acc[0][6]);
                acc[1][6] = ffma2(xp1, ws, acc[1][6]);
                acc[2][6] = ffma2(xp2, ws, acc[2][6]);
                acc[3][6] = ffma2(xp3, ws, acc[3][6]);
                ws = pack2(w1.w, w1.w);
                acc[0][7] = ffma2(xp0, ws, acc[0][7]);
                acc[1][7] = ffma2(xp1, ws, acc[1][7]);
                acc[2][7] = ffma2(xp2, ws, acc[2][7]);
                acc[3][7] = ffma2(xp3, ws, acc[3][7]);
            }
            ipu += (size_t)IN_W * BB;   // next input row
            wp  += KK * CC;             // next weight u-row (80 floats)
        }
        ip += CSTRIDE;                  // next input channel
        // wp already advanced by 400 floats (5 rows x 80) = next channel
    }

    // ---- epilogue: stage to smem, then coalesced global writes ----
    // so[(b*16 + ko)*JT + pl]
    #pragma unroll
    for (int p = 0; p < 4; ++p) {
        #pragma unroll
        for (int k = 0; k < 8; ++k) {
            float lo, hi;
            unpack2(acc[p][k], lo, hi);
            const int b  = bq2 * 8 + 2 * p;
            const int ko = kh * 8 + k;
            so[((b    ) * CC + ko) * JT + pl] = lo;
            so[((b + 1) * CC + ko) * JT + pl] = hi;
        }
    }
    __syncthreads();

    // 2048 floats, 64 per thread: e = (b*16+ko)*JT + jj -> 16B runs per row
    // lane covers (rest0 = lane>>2, jj = lane&3); each it adds 8 to rest.
    const size_t obase = (size_t)i * OUT_W + j0;
    {
        const int jj    = lane & 3;
        int       rest  = lane >> 2;       // 0..7
        const float* sp = so + lane;
        float* op = out + obase + jj;
        #pragma unroll
        for (int it = 0; it < 64; ++it) {
            op[(size_t)rest * (OUT_H * OUT_W)] = sp[it * NTHREADS];
            rest += 8;                     // NTHREADS/JT per iteration
        }
    }
}

// ---------------------------------------------------------------------------
extern "C" void kernel_launch(void* const* d_in, const int* in_sizes, int n_in,
                              void* d_out, int out_size) {
    const float* in_spikes = (const float*)d_in[0];
    const float* weights   = (const float*)d_in[1];
    float* out             = (float*)d_out;

    transpose_kernel<<<dim3(CC, IN_H), 256>>>(in_spikes);
    lc_kernel<<<dim3(OUT_W / JT, OUT_H), NTHREADS>>>(weights, out);
}

// round 15
// speedup vs baseline: 1.0763x; 1.0763x over previous
#include <cuda_runtime.h>

// Problem constants
#define BB     32
#define CC     16
#define IN_H   64
#define IN_W   64
#define OUT_H  60
#define OUT_W  60
#define KK     5
#define JT     4               // pixels per block
#define NW     4               // warps per block (4-way channel split)
#define CPW    (CC / NW)       // channels per warp = 4
#define NTHREADS (32 * NW)     // 128
#define CSTRIDE ((size_t)IN_H * IN_W * BB)

typedef unsigned long long ull;

// Scratch: transposed input inT[c][y][x][b]  (batch contiguous 128B lines)
__device__ float g_inT[CC * IN_H * IN_W * BB];

// ---------------------------------------------------------------------------
// Pre-kernel: in[b][c][y][x] -> inT[c][y][x][b]
// ---------------------------------------------------------------------------
__global__ void transpose_kernel(const float* __restrict__ in) {
    __shared__ float s[IN_W][BB + 1];
    const int c = blockIdx.x;
    const int y = blockIdx.y;
    const int t = threadIdx.x;          // 256 threads

    #pragma unroll
    for (int it = 0; it < 8; ++it) {
        int n = t + it * 256;           // 0..2047
        int x = n & 63;
        int b = n >> 6;
        s[x][b] = in[((b * CC + c) * IN_H + y) * IN_W + x];
    }
    __syncthreads();

    float* dst = g_inT + (size_t)(c * IN_H + y) * IN_W * BB;
    #pragma unroll
    for (int it = 0; it < 8; ++it) {
        int n = t + it * 256;
        int b = n & 31;
        int x = n >> 5;
        dst[x * BB + b] = s[x][b];
    }
}

// ---------------------------------------------------------------------------
// f32x2 helpers
// ---------------------------------------------------------------------------
__device__ __forceinline__ ull ffma2(ull a, ull b, ull c) {
    ull d;
    asm("fma.rn.f32x2 %0, %1, %2, %3;" : "=l"(d) : "l"(a), "l"(b), "l"(c));
    return d;
}
__device__ __forceinline__ ull pack2(float x, float y) {
    ull r;
    asm("mov.b64 %0, {%1, %2};" : "=l"(r) : "f"(x), "f"(y));
    return r;
}
__device__ __forceinline__ void unpack2(ull v, float& x, float& y) {
    asm("mov.b64 {%0, %1}, %2;" : "=f"(x), "=f"(y) : "l"(v));
}

// XOR bank-swizzle: moves e bit 5 (kh) into bank bit 2 and bits 9-10 (bq2)
// into bank bits 3-4 -> conflict-free partial stores; bits 0-1 untouched so
// float4 quads stay contiguous for the read side (swz(4r+d) == swz(4r)+d).
__device__ __forceinline__ int swz(int e) {
    return e ^ ((e >> 3) & 4) ^ ((e >> 6) & 0x18);
}

// ---------------------------------------------------------------------------
// Main kernel.
//   grid (15, 60): block = 4 warps over a 4-pixel j-tile on row i.
//   Warp w computes channels {4w..4w+3} (4-way split of the C reduction).
//   lane = pl (pixel, 2b) x bq2 (batch octet, 2b) x kh (ko octet, 1b).
//   thread = 8 batches x 8 k_out = 32 f32x2 accumulators.
// Per (c,u,v): 2 input LDG.128 + 2 weight LDG.128 = 16 L1-cyc vs
//              32 FFMA2 = 16 SM-FMA-cyc  -> balanced 1:1.
// 3600 warps total (~24/SM), no barriers in the main loop; one smem
// reduction + coalesced STG.128 epilogue.
// ---------------------------------------------------------------------------
__global__ __launch_bounds__(NTHREADS, 5)
void lc_kernel(const float* __restrict__ wgt, float* __restrict__ out) {
    __shared__ float sp[NW * BB * CC * JT];   // 4 x 2048 floats = 32KB

    const int j0   = blockIdx.x * JT;
    const int i    = blockIdx.y;
    const int tid  = threadIdx.x;
    const int w    = tid >> 5;                  // warp -> channel group
    const int lane = tid & 31;
    const int pl   = lane >> 3;                 // pixel 0..3
    const int bq2  = (lane >> 1) & 3;           // batch octet 0..3
    const int kh   = lane & 1;                  // ko octet 0..1
    const int j    = j0 + pl;
    const int c0   = w * CPW;

    // input: g_inT[c][i+u][j+v][bq2*8 .. +7]
    const float* ip = g_inT + (size_t)c0 * CSTRIDE
                    + ((size_t)i * IN_W + j) * BB + bq2 * 8;
    // weights: wgt[(i*60+j)*6400 + c*400 + (u*5+v)*16 + kh*8 .. +7]
    const float* wp = wgt + (size_t)(i * OUT_W + j) * (CC * KK * KK * CC)
                    + c0 * (KK * KK * CC) + kh * 8;

    ull acc[4][8];
    #pragma unroll
    for (int p = 0; p < 4; ++p)
        #pragma unroll
        for (int k = 0; k < 8; ++k) acc[p][k] = 0ull;

    #pragma unroll 1
    for (int c = 0; c < CPW; ++c) {
        const float* ipu = ip;
        #pragma unroll 1
        for (int u = 0; u < KK; ++u) {
            #pragma unroll
            for (int v = 0; v < KK; ++v) {
                float4 x0 = *(const float4*)(ipu + v * BB);
                float4 x1 = *(const float4*)(ipu + v * BB + 4);
                float4 w0 = *(const float4*)(wp + v * 16);
                float4 w1 = *(const float4*)(wp + v * 16 + 4);

                ull xp0 = pack2(x0.x, x0.y);
                ull xp1 = pack2(x0.z, x0.w);
                ull xp2 = pack2(x1.x, x1.y);
                ull xp3 = pack2(x1.z, x1.w);

                ull ws;
                ws = pack2(w0.x, w0.x);
                acc[0][0] = ffma2(xp0, ws, acc[0][0]);
                acc[1][0] = ffma2(xp1, ws, acc[1][0]);
                acc[2][0] = ffma2(xp2, ws, acc[2][0]);
                acc[3][0] = ffma2(xp3, ws, acc[3][0]);
                ws = pack2(w0.y, w0.y);
                acc[0][1] = ffma2(xp0, ws, acc[0][1]);
                acc[1][1] = ffma2(xp1, ws, acc[1][1]);
                acc[2][1] = ffma2(xp2, ws, acc[2][1]);
                acc[3][1] = ffma2(xp3, ws, acc[3][1]);
                ws = pack2(w0.z, w0.z);
                acc[0][2] = ffma2(xp0, ws, acc[0][2]);
                acc[1][2] = ffma2(xp1, ws, acc[1][2]);
                acc[2][2] = ffma2(xp2, ws, acc[2][2]);
                acc[3][2] = ffma2(xp3, ws, acc[3][2]);
                ws = pack2(w0.w, w0.w);
                acc[0][3] = ffma2(xp0, ws, acc[0][3]);
                acc[1][3] = ffma2(xp1, ws, acc[1][3]);
                acc[2][3] = ffma2(xp2, ws, acc[2][3]);
                acc[3][3] = ffma2(xp3, ws, acc[3][3]);
                ws = pack2(w1.x, w1.x);
                acc[0][4] = ffma2(xp0, ws, acc[0][4]);
                acc[1][4] = ffma2(xp1, ws, acc[1][4]);
                acc[2][4] = ffma2(xp2, ws, acc[2][4]);
                acc[3][4] = ffma2(xp3, ws, acc[3][4]);
                ws = pack2(w1.y, w1.y);
                acc[0][5] = ffma2(xp0, ws, acc[0][5]);
                acc[1][5] = ffma2(xp1, ws, acc[1][5]);
                acc[2][5] = ffma2(xp2, ws, acc[2][5]);
                acc[3][5] = ffma2(xp3, ws, acc[3][5]);
                ws = pack2(w1.z, w1.z);
                acc[0][6] = ffma2(xp0, ws, acc[0][6]);
                acc[1][6] = ffma2(xp1, ws, acc[1][6]);
                acc[2][6] = ffma2(xp2, ws, acc[2][6]);
                acc[3][6] = ffma2(xp3, ws, acc[3][6]);
                ws = pack2(w1.w, w1.w);
                acc[0][7] = ffma2(xp0, ws, acc[0][7]);
                acc[1][7] = ffma2(xp1, ws, acc[1][7]);
                acc[2][7] = ffma2(xp2, ws, acc[2][7]);
                acc[3][7] = ffma2(xp3, ws, acc[3][7]);
            }
            ipu += (size_t)IN_W * BB;   // next input row
            wp  += KK * CC;             // next weight u-row (80 floats)
        }
        ip += CSTRIDE;                  // next input channel
        // wp already advanced 400 floats = next channel
    }

    // ---- store per-warp partials into sp[w] with bank swizzle ----
    {
        float* spw = sp + w * (BB * CC * JT);
        #pragma unroll
        for (int p = 0; p < 4; ++p) {
            #pragma unroll
            for (int k = 0; k < 8; ++k) {
                float lo, hi;
                unpack2(acc[p][k], lo, hi);
                const int b  = bq2 * 8 + 2 * p;
                const int ko = kh * 8 + k;
                spw[swz(((b    ) * CC + ko) * JT + pl)] = lo;
                spw[swz(((b + 1) * CC + ko) * JT + pl)] = hi;
            }
        }
    }
    __syncthreads();

    // ---- reduce 4 partial planes + coalesced STG.128 epilogue ----
    // rest = b*16+ko (512 values); each thread handles 4 rests, one float4
    // (4 output columns) per rest.
    const size_t obase = (size_t)i * OUT_W + j0;
    #pragma unroll
    for (int it = 0; it < 4; ++it) {
        const int rest = tid + it * NTHREADS;     // 0..511
        const int es = swz(rest * 4);             // quad-aligned (bits 0-1 kept)
        float4 s0 = *(const float4*)(sp + es);
        float4 s1 = *(const float4*)(sp + 2048 + es);
        float4 s2 = *(const float4*)(sp + 4096 + es);
        float4 s3 = *(const float4*)(sp + 6144 + es);
        float4 r;
        r.x = (s0.x + s1.x) + (s2.x + s3.x);
        r.y = (s0.y + s1.y) + (s2.y + s3.y);
        r.z = (s0.z + s1.z) + (s2.z + s3.z);
        r.w = (s0.w + s1.w) + (s2.w + s3.w);
        *(float4*)(out + (size_t)rest * (OUT_H * OUT_W) + obase) = r;
    }
}

// ---------------------------------------------------------------------------
extern "C" void kernel_launch(void* const* d_in, const int* in_sizes, int n_in,
                              void* d_out, int out_size) {
    const float* in_spikes = (const float*)d_in[0];
    const float* weights   = (const float*)d_in[1];
    float* out             = (float*)d_out;

    transpose_kernel<<<dim3(CC, IN_H), 256>>>(in_spikes);
    lc_kernel<<<dim3(OUT_W / JT, OUT_H), NTHREADS>>>(weights, out);
}

// round 16
// speedup vs baseline: 2.6620x; 2.4733x over previous
#include <cuda_runtime.h>
#include <cstdint>

// Problem constants
#define BB     32
#define CC     16
#define IN_H   64
#define IN_W   64
#define OUT_H  60
#define OUT_W  60
#define KK     5
#define JT     4               // pixels per block
#define NW     4               // warps per block (4-way channel split)
#define NTHREADS (32 * NW)     // 128
#define CSTRIDE ((size_t)IN_H * IN_W * BB)
#define ROWSTR  (IN_W * BB)    // 2048 floats per input row

// Pipeline geometry
#define NSTG    4              // ring depth
#define TSTG    20             // total stages = (CC/NW) channels x KK rows
#define WSTG_W  320            // weight floats per warp-stage (4px x 80)
#define WSTG_C  (WSTG_W * NW)  // 1280 floats per CTA stage
#define ISTG_W  256            // input floats per warp-stage (8x x 32b)
#define ISTG_C  (ISTG_W * NW)  // 1024
#define IOFF    (NSTG * WSTG_C)          // 5120: input stages start here
#define SMEMF   (IOFF + NSTG * ISTG_C)   // 9216 floats (36.9KB); aliases 8192-float partials

typedef unsigned long long ull;

// Scratch: transposed input inT[c][y][x][b]  (batch contiguous 128B lines)
__device__ float g_inT[CC * IN_H * IN_W * BB];

// ---------------------------------------------------------------------------
// Pre-kernel: in[b][c][y][x] -> inT[c][y][x][b]
// ---------------------------------------------------------------------------
__global__ void transpose_kernel(const float* __restrict__ in) {
    __shared__ float s[IN_W][BB + 1];
    const int c = blockIdx.x;
    const int y = blockIdx.y;
    const int t = threadIdx.x;          // 256 threads

    #pragma unroll
    for (int it = 0; it < 8; ++it) {
        int n = t + it * 256;
        int x = n & 63;
        int b = n >> 6;
        s[x][b] = in[((b * CC + c) * IN_H + y) * IN_W + x];
    }
    __syncthreads();

    float* dst = g_inT + (size_t)(c * IN_H + y) * IN_W * BB;
    #pragma unroll
    for (int it = 0; it < 8; ++it) {
        int n = t + it * 256;
        int b = n & 31;
        int x = n >> 5;
        dst[x * BB + b] = s[x][b];
    }
}

// ---------------------------------------------------------------------------
// helpers
// ---------------------------------------------------------------------------
__device__ __forceinline__ ull ffma2(ull a, ull b, ull c) {
    ull d;
    asm("fma.rn.f32x2 %0, %1, %2, %3;" : "=l"(d) : "l"(a), "l"(b), "l"(c));
    return d;
}
__device__ __forceinline__ ull pack2(float x, float y) {
    ull r;
    asm("mov.b64 %0, {%1, %2};" : "=l"(r) : "f"(x), "f"(y));
    return r;
}
__device__ __forceinline__ void unpack2(ull v, float& x, float& y) {
    asm("mov.b64 {%0, %1}, %2;" : "=f"(x), "=f"(y) : "l"(v));
}
__device__ __forceinline__ void cpasync16(uint32_t dst, const void* src) {
    asm volatile("cp.async.cg.shared.global [%0], [%1], 16;" :: "r"(dst), "l"(src));
}
#define CP_COMMIT() asm volatile("cp.async.commit_group;")
#define CP_WAIT2()  asm volatile("cp.async.wait_group 2;")

// XOR bank-swizzle for the partial-sum reduction (verified conflict-free,
// quad-preserving: swz(4r+d) == swz(4r)+d).
__device__ __forceinline__ int swz(int e) {
    return e ^ ((e >> 3) & 4) ^ ((e >> 6) & 0x18);
}

// ---------------------------------------------------------------------------
// Main kernel: cp.async software pipeline.
//   grid (15, 60): 4 warps over a 4-pixel j-tile; warp w owns channels 4w..4w+3.
//   lane = pl(2b pixel) x bq2(2b batch octet) x kh(1b ko octet);
//   thread = 8 batches x 8 ko = 32 f32x2 accumulators.
// Stage = (c,u): weights (4px x 80 fl) + input row (8x x 32b), staged 4 deep
// via cp.async. Inner loop is pure LDS.128 + FFMA2 (all latencies <= 29cyc).
// ---------------------------------------------------------------------------
__global__ __launch_bounds__(NTHREADS, 4)
void lc_kernel(const float* __restrict__ wgt, float* __restrict__ out) {
    __shared__ __align__(16) float smem[SMEMF];

    const int j0   = blockIdx.x * JT;
    const int i    = blockIdx.y;
    const int tid  = threadIdx.x;
    const int w    = tid >> 5;
    const int lane = tid & 31;
    const int pl   = lane >> 3;
    const int bq2  = (lane >> 1) & 3;
    const int kh   = lane & 1;

    const uint32_t sb = (uint32_t)__cvta_generic_to_shared(smem);

    // ---- loader precompute (per thread, fixed across stages) ----
    // weights: 320 float4 per CTA stage, rounds n = tid, tid+128, tid+256(<320)
    const float*  wsrcb[3];
    uint32_t      wdstb[3];
    #pragma unroll
    for (int r = 0; r < 3; ++r) {
        int n = tid + r * NTHREADS;
        if (n >= 320) n = 0;            // inactive round (r==2, tid>=64): dummy
        int wl = n / 80, rr = n % 80;
        int px = rr / 20, f4 = rr % 20;
        wsrcb[r] = wgt + (size_t)(i * OUT_W + j0 + px) * (CC * KK * KK * CC)
                 + wl * (4 * KK * KK * CC)          // channel base 4*wl*400
                 + f4 * 4;
        wdstb[r] = sb + 4 * (wl * WSTG_W + px * 80 + f4 * 4);
    }
    const bool wact2 = (tid + 2 * NTHREADS) < 320;
    // inputs: 256 float4 per CTA stage, rounds n = tid, tid+128
    const float*  isrcb[2];
    uint32_t      idstb[2];
    #pragma unroll
    for (int r = 0; r < 2; ++r) {
        int n = tid + r * NTHREADS;
        int wl = n / 64, rr = n % 64;
        isrcb[r] = g_inT + (size_t)(4 * wl) * CSTRIDE
                 + ((size_t)i * IN_W + j0) * BB + rr * 4;
        idstb[r] = sb + 4 * (IOFF + wl * ISTG_W + rr * 4);
    }

    // stage-walk state for the loader: stage t3 -> weights +80*t3 floats,
    // inputs + c*CSTRIDE + u*ROWSTR.
    int    u3 = 0;
    size_t io3 = 0;

    #define LOAD_STAGE(T3)                                                     \
        do {                                                                   \
            if ((T3) < TSTG) {                                                 \
                const int      _slot = (T3) & (NSTG - 1);                      \
                const uint32_t _wso  = _slot * (WSTG_C * 4);                   \
                const uint32_t _iso  = _slot * (ISTG_C * 4);                   \
                const size_t   _wof  = (size_t)(T3) * 80;                      \
                cpasync16(wdstb[0] + _wso, wsrcb[0] + _wof);                   \
                cpasync16(wdstb[1] + _wso, wsrcb[1] + _wof);                   \
                if (wact2) cpasync16(wdstb[2] + _wso, wsrcb[2] + _wof);        \
                cpasync16(idstb[0] + _iso, isrcb[0] + io3);                    \
                cpasync16(idstb[1] + _iso, isrcb[1] + io3);                    \
                io3 += ROWSTR;                                                 \
                if (++u3 == KK) { u3 = 0; io3 += CSTRIDE - KK * ROWSTR; }      \
            }                                                                  \
            CP_COMMIT();                                                       \
        } while (0)

    // ---- prime 3 stages ----
    LOAD_STAGE(0);
    LOAD_STAGE(1);
    LOAD_STAGE(2);

    ull acc[4][8];
    #pragma unroll
    for (int p = 0; p < 4; ++p)
        #pragma unroll
        for (int k = 0; k < 8; ++k) acc[p][k] = 0ull;

    // per-thread consumption bases (float4 indices)
    const int wqb = (w * WSTG_W + pl * 80 + kh * 8) >> 2;   // + slot*320 + v*4
    const int iqb = (IOFF + w * ISTG_W + pl * BB + bq2 * 8) >> 2; // + slot*256 + v*8

    #pragma unroll 1
    for (int t = 0; t < TSTG; ++t) {
        CP_WAIT2();              // stage t complete (3 groups in flight max)
        __syncthreads();         // visible CTA-wide; slot (t+3)%4 free
        LOAD_STAGE(t + 3);

        const int slot = t & (NSTG - 1);
        const float4* wq = (const float4*)smem + slot * (WSTG_C / 4) + wqb;
        const float4* iq = (const float4*)smem + slot * (ISTG_C / 4) + iqb;

        #pragma unroll
        for (int v = 0; v < KK; ++v) {
            float4 x0 = iq[v * 8];
            float4 x1 = iq[v * 8 + 1];
            float4 w0 = wq[v * 4];
            float4 w1 = wq[v * 4 + 1];

            ull xp0 = pack2(x0.x, x0.y);
            ull xp1 = pack2(x0.z, x0.w);
            ull xp2 = pack2(x1.x, x1.y);
            ull xp3 = pack2(x1.z, x1.w);

            ull ws;
            ws = pack2(w0.x, w0.x);
            acc[0][0] = ffma2(xp0, ws, acc[0][0]);
            acc[1][0] = ffma2(xp1, ws, acc[1][0]);
            acc[2][0] = ffma2(xp2, ws, acc[2][0]);
            acc[3][0] = ffma2(xp3, ws, acc[3][0]);
            ws = pack2(w0.y, w0.y);
            acc[0][1] = ffma2(xp0, ws, acc[0][1]);
            acc[1][1] = ffma2(xp1, ws, acc[1][1]);
            acc[2][1] = ffma2(xp2, ws, acc[2][1]);
            acc[3][1] = ffma2(xp3, ws, acc[3][1]);
            ws = pack2(w0.z, w0.z);
            acc[0][2] = ffma2(xp0, ws, acc[0][2]);
            acc[1][2] = ffma2(xp1, ws, acc[1][2]);
            acc[2][2] = ffma2(xp2, ws, acc[2][2]);
            acc[3][2] = ffma2(xp3, ws, acc[3][2]);
            ws = pack2(w0.w, w0.w);
            acc[0][3] = ffma2(xp0, ws, acc[0][3]);
            acc[1][3] = ffma2(xp1, ws, acc[1][3]);
            acc[2][3] = ffma2(xp2, ws, acc[2][3]);
            acc[3][3] = ffma2(xp3, ws, acc[3][3]);
            ws = pack2(w1.x, w1.x);
            acc[0][4] = ffma2(xp0, ws, acc[0][4]);
            acc[1][4] = ffma2(xp1, ws, acc[1][4]);
            acc[2][4] = ffma2(xp2, ws, acc[2][4]);
            acc[3][4] = ffma2(xp3, ws, acc[3][4]);
            ws = pack2(w1.y, w1.y);
            acc[0][5] = ffma2(xp0, ws, acc[0][5]);
            acc[1][5] = ffma2(xp1, ws, acc[1][5]);
            acc[2][5] = ffma2(xp2, ws, acc[2][5]);
            acc[3][5] = ffma2(xp3, ws, acc[3][5]);
            ws = pack2(w1.z, w1.z);
            acc[0][6] = ffma2(xp0, ws, acc[0][6]);
            acc[1][6] = ffma2(xp1, ws, acc[1][6]);
            acc[2][6] = ffma2(xp2, ws, acc[2][6]);
            acc[3][6] = ffma2(xp3, ws, acc[3][6]);
            ws = pack2(w1.w, w1.w);
            acc[0][7] = ffma2(xp0, ws, acc[0][7]);
            acc[1][7] = ffma2(xp1, ws, acc[1][7]);
            acc[2][7] = ffma2(xp2, ws, acc[2][7]);
            acc[3][7] = ffma2(xp3, ws, acc[3][7]);
        }
    }
    #undef LOAD_STAGE

    // ---- epilogue: partials into (aliased) smem with bank swizzle ----
    __syncthreads();             // everyone done reading stage buffers
    {
        float* spw = smem + w * (BB * CC * JT);
        #pragma unroll
        for (int p = 0; p < 4; ++p) {
            #pragma unroll
            for (int k = 0; k < 8; ++k) {
                float lo, hi;
                unpack2(acc[p][k], lo, hi);
                const int b  = bq2 * 8 + 2 * p;
                const int ko = kh * 8 + k;
                spw[swz(((b    ) * CC + ko) * JT + pl)] = lo;
                spw[swz(((b + 1) * CC + ko) * JT + pl)] = hi;
            }
        }
    }
    __syncthreads();

    // ---- reduce 4 partial planes + coalesced STG.128 ----
    const size_t obase = (size_t)i * OUT_W + j0;
    #pragma unroll
    for (int it = 0; it < 4; ++it) {
        const int rest = tid + it * NTHREADS;     // 0..511 = b*16+ko
        const int es = swz(rest * 4);
        float4 s0 = *(const float4*)(smem + es);
        float4 s1 = *(const float4*)(smem + 2048 + es);
        float4 s2 = *(const float4*)(smem + 4096 + es);
        float4 s3 = *(const float4*)(smem + 6144 + es);
        float4 r;
        r.x = (s0.x + s1.x) + (s2.x + s3.x);
        r.y = (s0.y + s1.y) + (s2.y + s3.y);
        r.z = (s0.z + s1.z) + (s2.z + s3.z);
        r.w = (s0.w + s1.w) + (s2.w + s3.w);
        *(float4*)(out + (size_t)rest * (OUT_H * OUT_W) + obase) = r;
    }
}

// ---------------------------------------------------------------------------
extern "C" void kernel_launch(void* const* d_in, const int* in_sizes, int n_in,
                              void* d_out, int out_size) {
    const float* in_spikes = (const float*)d_in[0];
    const float* weights   = (const float*)d_in[1];
    float* out             = (float*)d_out;

    transpose_kernel<<<dim3(CC, IN_H), 256>>>(in_spikes);
    lc_kernel<<<dim3(OUT_W / JT, OUT_H), NTHREADS>>>(weights, out);
}